// round 9
// baseline (speedup 1.0000x reference)
#include <cuda_runtime.h>

// SparseBiasDiagUnfolder: gather off-diagonal 8x8 window entries.
// adj: (B=2, N=2048, N=2048, F=16) f32
// out: (B=2, S=511, 56*16=896) f32
// out[b, s, k*16+f] = adj[b, 4*s + ii(k), 4*s + jj(k), f]
// local = k + 1 + k/8 (skips diagonal multiples of 9), ii = local/8, jj = local%8.
//
// TOT4 = 2*511*56*4 = 228928 float4 outputs.
// TPB=224 (7 warps), U=4 -> 256 blocks: 255 full blocks take a guard-free
// path (4 front-batched independent LDG.128s per thread, MLP_p1=4), the
// single tail block (448 remaining float4s) takes a predicated path behind
// a uniform branch. ~12 warps/SM x MLP 4 ~= 24 KB/SM in flight; stride-TPB
// mapping keeps STG.128s fully coalesced.

namespace {
constexpr int B  = 2;
constexpr int N  = 2048;
constexpr int S  = 511;
constexpr int K  = 56;
constexpr int TOT4 = B * S * K * 4;              // 228928
constexpr int U  = 4;
constexpr int TPB = 224;
constexpr int PER_BLOCK = TPB * U;               // 896
constexpr int BLOCKS = (TOT4 + PER_BLOCK - 1) / PER_BLOCK;  // 256
}

__device__ __forceinline__ int src_index(int t) {
    int f4   = t & 3;            // float4 within the 16-float feature vec
    int t2   = t >> 2;           // (b, s, k)
    int k    = t2 % K;
    int rest = t2 / K;
    int s    = rest % S;
    int b    = rest / S;

    int local = k + 1 + (k >> 3);    // skip diagonal
    int r = (s << 2) + (local >> 3);
    int c = (s << 2) + (local & 7);
    return (((b * N) + r) * N + c) * 4 + f4;
}

__global__ void __launch_bounds__(TPB)
sparse_diag_unfold_kernel(const float4* __restrict__ adj4,
                          float4* __restrict__ out4) {
    const int base = blockIdx.x * PER_BLOCK + threadIdx.x;

    if (blockIdx.x != BLOCKS - 1) {
        // Full block: guard-free, front-batched independent loads.
        float4 v[U];
        #pragma unroll
        for (int u = 0; u < U; u++) {
            v[u] = __ldg(&adj4[src_index(base + u * TPB)]);
        }
        #pragma unroll
        for (int u = 0; u < U; u++) {
            out4[base + u * TPB] = v[u];
        }
    } else {
        // Tail block: predicated.
        float4 v[U];
        #pragma unroll
        for (int u = 0; u < U; u++) {
            int t = base + u * TPB;
            if (t < TOT4) v[u] = __ldg(&adj4[src_index(t)]);
        }
        #pragma unroll
        for (int u = 0; u < U; u++) {
            int t = base + u * TPB;
            if (t < TOT4) out4[t] = v[u];
        }
    }
}

extern "C" void kernel_launch(void* const* d_in, const int* in_sizes, int n_in,
                              void* d_out, int out_size) {
    const float4* adj4 = (const float4*)d_in[0];
    float4* out4 = (float4*)d_out;
    sparse_diag_unfold_kernel<<<BLOCKS, TPB>>>(adj4, out4);
}